// round 1
// baseline (speedup 1.0000x reference)
#include <cuda_runtime.h>

#define NPIX 4096
#define CIN 256
#define CQK 64
#define BATCH 4

// Scratch (device globals — no allocation allowed in kernel_launch)
__device__ float g_q[BATCH * CQK * NPIX];
__device__ float g_k[BATCH * CQK * NPIX];
__device__ float g_v[BATCH * CIN * NPIX];
__device__ float g_att[BATCH * CIN * NPIX];

// ---------------------------------------------------------------------------
// Generic 1x1-conv GEMM: C[b][o][n] = sum_c W[o][c] * X[b][c][n] + bias[o]
// grid (NPIX/64, M/64, BATCH), block 256 threads, 64x64 tile, K-step 16.
// ---------------------------------------------------------------------------
__global__ __launch_bounds__(256) void gemm_wx(
    const float* __restrict__ W, const float* __restrict__ bias,
    const float* __restrict__ X, float* __restrict__ C, int M) {
    __shared__ float Ws[16][68];  // [kk][o]
    __shared__ float Xs[16][68];  // [kk][n]

    const int b  = blockIdx.z;
    const int n0 = blockIdx.x * 64;
    const int o0 = blockIdx.y * 64;
    const float* Xb = X + (size_t)b * CIN * NPIX;
    float* Cb       = C + (size_t)b * M * NPIX;

    const int t  = threadIdx.x;
    const int tx = t % 16;       // n micro-tile
    const int ty = t / 16;       // o micro-tile

    float acc[4][4] = {};

    for (int c0 = 0; c0 < CIN; c0 += 16) {
        // Load W tile (64 o x 16 c), coalesced along c
        {
            int cc = t % 16;
            int ob = t / 16;
#pragma unroll
            for (int r = 0; r < 4; r++) {
                int o = ob + 16 * r;
                Ws[cc][o] = W[(o0 + o) * CIN + c0 + cc];
            }
        }
        // Load X tile (16 c x 64 n), coalesced along n
        {
            int nn = t % 64;
            int cb = t / 64;
#pragma unroll
            for (int r = 0; r < 4; r++) {
                int cc = cb + 4 * r;
                Xs[cc][nn] = Xb[(size_t)(c0 + cc) * NPIX + n0 + nn];
            }
        }
        __syncthreads();

#pragma unroll
        for (int kk = 0; kk < 16; kk++) {
            float4 wv = *(const float4*)&Ws[kk][ty * 4];
            float4 xv = *(const float4*)&Xs[kk][tx * 4];
            float wa[4] = {wv.x, wv.y, wv.z, wv.w};
            float xa[4] = {xv.x, xv.y, xv.z, xv.w};
#pragma unroll
            for (int i = 0; i < 4; i++)
#pragma unroll
                for (int j = 0; j < 4; j++)
                    acc[i][j] += wa[i] * xa[j];
        }
        __syncthreads();
    }

#pragma unroll
    for (int i = 0; i < 4; i++) {
        float bo = bias[o0 + ty * 4 + i];
        float4 r = make_float4(acc[i][0] + bo, acc[i][1] + bo,
                               acc[i][2] + bo, acc[i][3] + bo);
        *(float4*)&Cb[(size_t)(o0 + ty * 4 + i) * NPIX + n0 + tx * 4] = r;
    }
}

// ---------------------------------------------------------------------------
// Fused attention:
//   energy[n,m] = elu( sum_o q[o,n]*k[o,m] ) / NPIX
//   att[c,m]   = sum_n v[c,n] * energy[n,m]
// One block per (m-tile of 64, batch). k tile resident; stream n in chunks of 16.
// Each thread owns an 8(c) x 8(m) accumulator of the 256x64 output tile.
// ---------------------------------------------------------------------------
__global__ __launch_bounds__(256, 2) void attn_fused(
    const float* __restrict__ q, const float* __restrict__ k,
    const float* __restrict__ v, float* __restrict__ att) {
    __shared__ float k_s[64][68];   // [o][m]
    __shared__ float q_s[64][17];   // [o][i]
    __shared__ float e_s[16][68];   // [i][m]
    __shared__ float v_s[256][17];  // [c][i]

    const int b  = blockIdx.y;
    const int m0 = blockIdx.x * 64;
    const float* qb = q + (size_t)b * CQK * NPIX;
    const float* kb = k + (size_t)b * CQK * NPIX;
    const float* vb = v + (size_t)b * CIN * NPIX;
    float* ab       = att + (size_t)b * CIN * NPIX;

    const int t = threadIdx.x;

    // Load k tile once: 64 o x 64 m
    {
        int j  = t % 64;
        int ob = t / 64;
#pragma unroll
        for (int r = 0; r < 16; r++) {
            int o = ob + 4 * r;
            k_s[o][j] = kb[(size_t)o * NPIX + m0 + j];
        }
    }
    __syncthreads();

    const int tc = t / 8;        // 0..31 -> c0 = tc*8
    const int tm = t % 8;        // 0..7  -> mt = tm*8
    const int c0 = tc * 8;
    const int mt = tm * 8;

    float acc[8][8] = {};

    const int i16  = t % 16;
    const int g16  = t / 16;

    for (int n0 = 0; n0 < NPIX; n0 += 16) {
        // Load q chunk: 64 o x 16 n
#pragma unroll
        for (int r = 0; r < 4; r++) {
            int o = g16 + 16 * r;
            q_s[o][i16] = qb[(size_t)o * NPIX + n0 + i16];
        }
        // Load v chunk: 256 c x 16 n
#pragma unroll
        for (int r = 0; r < 16; r++) {
            int c = g16 + 16 * r;
            v_s[c][i16] = vb[(size_t)c * NPIX + n0 + i16];
        }
        __syncthreads();

        // Stage 1: E (16 n x 64 m), each thread 1x4
        {
            int js = g16 * 4;
            float a0 = 0.f, a1 = 0.f, a2 = 0.f, a3 = 0.f;
#pragma unroll
            for (int o = 0; o < 64; o++) {
                float qv = q_s[o][i16];
                float4 kv = *(const float4*)&k_s[o][js];
                a0 += qv * kv.x;
                a1 += qv * kv.y;
                a2 += qv * kv.z;
                a3 += qv * kv.w;
            }
            const float inv = 1.0f / (float)NPIX;
            a0 = (a0 > 0.f ? a0 : expm1f(a0)) * inv;
            a1 = (a1 > 0.f ? a1 : expm1f(a1)) * inv;
            a2 = (a2 > 0.f ? a2 : expm1f(a2)) * inv;
            a3 = (a3 > 0.f ? a3 : expm1f(a3)) * inv;
            *(float4*)&e_s[i16][js] = make_float4(a0, a1, a2, a3);
        }
        __syncthreads();

        // Stage 2: acc[c][m] += v[c][i] * E[i][m]
#pragma unroll
        for (int i = 0; i < 16; i++) {
            float4 e0 = *(const float4*)&e_s[i][mt];
            float4 e1 = *(const float4*)&e_s[i][mt + 4];
            float ea[8] = {e0.x, e0.y, e0.z, e0.w, e1.x, e1.y, e1.z, e1.w};
#pragma unroll
            for (int u = 0; u < 8; u++) {
                float vv = v_s[c0 + u][i];
#pragma unroll
                for (int j = 0; j < 8; j++)
                    acc[u][j] += vv * ea[j];
            }
        }
        __syncthreads();
    }

    // Epilogue: write att tile
#pragma unroll
    for (int u = 0; u < 8; u++) {
        float4 r0 = make_float4(acc[u][0], acc[u][1], acc[u][2], acc[u][3]);
        float4 r1 = make_float4(acc[u][4], acc[u][5], acc[u][6], acc[u][7]);
        size_t base = (size_t)(c0 + u) * NPIX + m0 + mt;
        *(float4*)&ab[base]     = r0;
        *(float4*)&ab[base + 4] = r1;
    }
}

extern "C" void kernel_launch(void* const* d_in, const int* in_sizes, int n_in,
                              void* d_out, int out_size) {
    const float* x  = (const float*)d_in[0];
    const float* wq = (const float*)d_in[1];
    const float* bq = (const float*)d_in[2];
    const float* wk = (const float*)d_in[3];
    const float* bk = (const float*)d_in[4];
    const float* wv = (const float*)d_in[5];
    const float* bv = (const float*)d_in[6];
    const float* wg = (const float*)d_in[7];
    const float* bg = (const float*)d_in[8];
    float* out = (float*)d_out;

    float *q, *k, *v, *att;
    cudaGetSymbolAddress((void**)&q, g_q);
    cudaGetSymbolAddress((void**)&k, g_k);
    cudaGetSymbolAddress((void**)&v, g_v);
    cudaGetSymbolAddress((void**)&att, g_att);

    // q, k, v projections (1x1 convs)
    gemm_wx<<<dim3(NPIX / 64, CQK / 64, BATCH), 256>>>(wq, bq, x, q, CQK);
    gemm_wx<<<dim3(NPIX / 64, CQK / 64, BATCH), 256>>>(wk, bk, x, k, CQK);
    gemm_wx<<<dim3(NPIX / 64, CIN / 64, BATCH), 256>>>(wv, bv, x, v, CIN);

    // fused energy + weighted sum
    attn_fused<<<dim3(NPIX / 64, BATCH), 256>>>(q, k, v, att);

    // output projection
    gemm_wx<<<dim3(NPIX / 64, CIN / 64, BATCH), 256>>>(wg, bg, att, out, CIN);
}

// round 2
// speedup vs baseline: 1.0015x; 1.0015x over previous
#include <cuda_runtime.h>

#define NPIX 4096
#define CIN 256
#define CQK 64
#define BATCH 4

// Scratch (device globals — no allocation allowed in kernel_launch)
__device__ float g_q[BATCH * CQK * NPIX];
__device__ float g_k[BATCH * CQK * NPIX];
__device__ float g_v[BATCH * CIN * NPIX];
__device__ float g_att[BATCH * CIN * NPIX];

// ---------------------------------------------------------------------------
// Generic 1x1-conv GEMM: C[b][o][n] = sum_c W[o][c] * X[b][c][n] + bias[o]
// grid (NPIX/64, M/64, BATCH), block 256 threads, 64x64 tile, K-step 16.
// ---------------------------------------------------------------------------
__global__ __launch_bounds__(256) void gemm_wx(
    const float* __restrict__ W, const float* __restrict__ bias,
    const float* __restrict__ X, float* __restrict__ C, int M) {
    __shared__ float Ws[16][68];  // [kk][o]
    __shared__ float Xs[16][68];  // [kk][n]

    const int b  = blockIdx.z;
    const int n0 = blockIdx.x * 64;
    const int o0 = blockIdx.y * 64;
    const float* Xb = X + (size_t)b * CIN * NPIX;
    float* Cb       = C + (size_t)b * M * NPIX;

    const int t  = threadIdx.x;
    const int tx = t % 16;       // n micro-tile
    const int ty = t / 16;       // o micro-tile

    float acc[4][4] = {};

    for (int c0 = 0; c0 < CIN; c0 += 16) {
        // Load W tile (64 o x 16 c), coalesced along c
        {
            int cc = t % 16;
            int ob = t / 16;
#pragma unroll
            for (int r = 0; r < 4; r++) {
                int o = ob + 16 * r;
                Ws[cc][o] = W[(o0 + o) * CIN + c0 + cc];
            }
        }
        // Load X tile (16 c x 64 n), coalesced along n
        {
            int nn = t % 64;
            int cb = t / 64;
#pragma unroll
            for (int r = 0; r < 4; r++) {
                int cc = cb + 4 * r;
                Xs[cc][nn] = Xb[(size_t)(c0 + cc) * NPIX + n0 + nn];
            }
        }
        __syncthreads();

#pragma unroll
        for (int kk = 0; kk < 16; kk++) {
            float4 wv = *(const float4*)&Ws[kk][ty * 4];
            float4 xv = *(const float4*)&Xs[kk][tx * 4];
            float wa[4] = {wv.x, wv.y, wv.z, wv.w};
            float xa[4] = {xv.x, xv.y, xv.z, xv.w};
#pragma unroll
            for (int i = 0; i < 4; i++)
#pragma unroll
                for (int j = 0; j < 4; j++)
                    acc[i][j] += wa[i] * xa[j];
        }
        __syncthreads();
    }

#pragma unroll
    for (int i = 0; i < 4; i++) {
        float bo = bias[o0 + ty * 4 + i];
        float4 r = make_float4(acc[i][0] + bo, acc[i][1] + bo,
                               acc[i][2] + bo, acc[i][3] + bo);
        *(float4*)&Cb[(size_t)(o0 + ty * 4 + i) * NPIX + n0 + tx * 4] = r;
    }
}

// ---------------------------------------------------------------------------
// Fused attention:
//   energy[n,m] = elu( sum_o q[o,n]*k[o,m] ) / NPIX
//   att[c,m]   = sum_n v[c,n] * energy[n,m]
// One block per (m-tile of 64, batch). k tile resident; stream n in chunks of 16.
// Each thread owns an 8(c) x 8(m) accumulator of the 256x64 output tile.
// ---------------------------------------------------------------------------
__global__ __launch_bounds__(256, 2) void attn_fused(
    const float* __restrict__ q, const float* __restrict__ k,
    const float* __restrict__ v, float* __restrict__ att) {
    __shared__ float k_s[64][68];   // [o][m]
    __shared__ float q_s[64][17];   // [o][i]
    __shared__ float e_s[16][68];   // [i][m]
    __shared__ float v_s[256][17];  // [c][i]

    const int b  = blockIdx.y;
    const int m0 = blockIdx.x * 64;
    const float* qb = q + (size_t)b * CQK * NPIX;
    const float* kb = k + (size_t)b * CQK * NPIX;
    const float* vb = v + (size_t)b * CIN * NPIX;
    float* ab       = att + (size_t)b * CIN * NPIX;

    const int t = threadIdx.x;

    // Load k tile once: 64 o x 64 m
    {
        int j  = t % 64;
        int ob = t / 64;
#pragma unroll
        for (int r = 0; r < 16; r++) {
            int o = ob + 4 * r;
            k_s[o][j] = kb[(size_t)o * NPIX + m0 + j];
        }
    }
    __syncthreads();

    const int tc = t / 8;        // 0..31 -> c0 = tc*8
    const int tm = t % 8;        // 0..7  -> mt = tm*8
    const int c0 = tc * 8;
    const int mt = tm * 8;

    float acc[8][8] = {};

    const int i16  = t % 16;
    const int g16  = t / 16;

    for (int n0 = 0; n0 < NPIX; n0 += 16) {
        // Load q chunk: 64 o x 16 n
#pragma unroll
        for (int r = 0; r < 4; r++) {
            int o = g16 + 16 * r;
            q_s[o][i16] = qb[(size_t)o * NPIX + n0 + i16];
        }
        // Load v chunk: 256 c x 16 n
#pragma unroll
        for (int r = 0; r < 16; r++) {
            int c = g16 + 16 * r;
            v_s[c][i16] = vb[(size_t)c * NPIX + n0 + i16];
        }
        __syncthreads();

        // Stage 1: E (16 n x 64 m), each thread 1x4
        {
            int js = g16 * 4;
            float a0 = 0.f, a1 = 0.f, a2 = 0.f, a3 = 0.f;
#pragma unroll
            for (int o = 0; o < 64; o++) {
                float qv = q_s[o][i16];
                float4 kv = *(const float4*)&k_s[o][js];
                a0 += qv * kv.x;
                a1 += qv * kv.y;
                a2 += qv * kv.z;
                a3 += qv * kv.w;
            }
            const float inv = 1.0f / (float)NPIX;
            a0 = (a0 > 0.f ? a0 : expm1f(a0)) * inv;
            a1 = (a1 > 0.f ? a1 : expm1f(a1)) * inv;
            a2 = (a2 > 0.f ? a2 : expm1f(a2)) * inv;
            a3 = (a3 > 0.f ? a3 : expm1f(a3)) * inv;
            *(float4*)&e_s[i16][js] = make_float4(a0, a1, a2, a3);
        }
        __syncthreads();

        // Stage 2: acc[c][m] += v[c][i] * E[i][m]
#pragma unroll
        for (int i = 0; i < 16; i++) {
            float4 e0 = *(const float4*)&e_s[i][mt];
            float4 e1 = *(const float4*)&e_s[i][mt + 4];
            float ea[8] = {e0.x, e0.y, e0.z, e0.w, e1.x, e1.y, e1.z, e1.w};
#pragma unroll
            for (int u = 0; u < 8; u++) {
                float vv = v_s[c0 + u][i];
#pragma unroll
                for (int j = 0; j < 8; j++)
                    acc[u][j] += vv * ea[j];
            }
        }
        __syncthreads();
    }

    // Epilogue: write att tile
#pragma unroll
    for (int u = 0; u < 8; u++) {
        float4 r0 = make_float4(acc[u][0], acc[u][1], acc[u][2], acc[u][3]);
        float4 r1 = make_float4(acc[u][4], acc[u][5], acc[u][6], acc[u][7]);
        size_t base = (size_t)(c0 + u) * NPIX + m0 + mt;
        *(float4*)&ab[base]     = r0;
        *(float4*)&ab[base + 4] = r1;
    }
}

extern "C" void kernel_launch(void* const* d_in, const int* in_sizes, int n_in,
                              void* d_out, int out_size) {
    const float* x  = (const float*)d_in[0];
    const float* wq = (const float*)d_in[1];
    const float* bq = (const float*)d_in[2];
    const float* wk = (const float*)d_in[3];
    const float* bk = (const float*)d_in[4];
    const float* wv = (const float*)d_in[5];
    const float* bv = (const float*)d_in[6];
    const float* wg = (const float*)d_in[7];
    const float* bg = (const float*)d_in[8];
    float* out = (float*)d_out;

    float *q, *k, *v, *att;
    cudaGetSymbolAddress((void**)&q, g_q);
    cudaGetSymbolAddress((void**)&k, g_k);
    cudaGetSymbolAddress((void**)&v, g_v);
    cudaGetSymbolAddress((void**)&att, g_att);

    // q, k, v projections (1x1 convs)
    gemm_wx<<<dim3(NPIX / 64, CQK / 64, BATCH), 256>>>(wq, bq, x, q, CQK);
    gemm_wx<<<dim3(NPIX / 64, CQK / 64, BATCH), 256>>>(wk, bk, x, k, CQK);
    gemm_wx<<<dim3(NPIX / 64, CIN / 64, BATCH), 256>>>(wv, bv, x, v, CIN);

    // fused energy + weighted sum
    attn_fused<<<dim3(NPIX / 64, BATCH), 256>>>(q, k, v, att);

    // output projection
    gemm_wx<<<dim3(NPIX / 64, CIN / 64, BATCH), 256>>>(wg, bg, att, out, CIN);
}

// round 4
// speedup vs baseline: 4.2762x; 4.2699x over previous
#include <cuda_runtime.h>
#include <cuda_fp16.h>
#include <cstdint>

#define NPIX 4096
#define CIN  256
#define CQK  64
#define BATCH 4

// ------------------------- device scratch ----------------------------------
__device__ float  g_w2[CIN * CIN];
__device__ float  g_b2[CIN];
__device__ __half g_q[(size_t)BATCH * NPIX * CQK];   // [b][n][o]  fp16
__device__ __half g_k[(size_t)BATCH * NPIX * CQK];   // [b][m][o]  fp16
__device__ __half g_v[(size_t)BATCH * CIN * NPIX];   // [b][c][n]  fp16  (v' = (wg@wv)x + wg@bv)
__device__ __half g_e[(size_t)BATCH * NPIX * NPIX];  // [b][m][n]  fp16  (elu(energy), no /N)

// ------------------------- helpers -----------------------------------------
__device__ __forceinline__ uint32_t smem_u32(const void* p) {
    uint32_t a;
    asm("{ .reg .u64 t; cvta.to.shared.u64 t, %1; cvt.u32.u64 %0, t; }" : "=r"(a) : "l"(p));
    return a;
}
__device__ __forceinline__ void ldsm_x4(uint32_t a[4], uint32_t addr) {
    asm volatile("ldmatrix.sync.aligned.m8n8.x4.shared.b16 {%0,%1,%2,%3}, [%4];"
                 : "=r"(a[0]), "=r"(a[1]), "=r"(a[2]), "=r"(a[3]) : "r"(addr));
}
__device__ __forceinline__ void ldsm_x2(uint32_t a[2], uint32_t addr) {
    asm volatile("ldmatrix.sync.aligned.m8n8.x2.shared.b16 {%0,%1}, [%2];"
                 : "=r"(a[0]), "=r"(a[1]) : "r"(addr));
}
__device__ __forceinline__ void mma16816(float d[4], const uint32_t a[4], const uint32_t b[2]) {
    asm volatile(
        "mma.sync.aligned.m16n8k16.row.col.f32.f16.f16.f32 "
        "{%0,%1,%2,%3}, {%4,%5,%6,%7}, {%8,%9}, {%0,%1,%2,%3};"
        : "+f"(d[0]), "+f"(d[1]), "+f"(d[2]), "+f"(d[3])
        : "r"(a[0]), "r"(a[1]), "r"(a[2]), "r"(a[3]), "r"(b[0]), "r"(b[1]));
}
__device__ __forceinline__ float eluf(float x) { return x > 0.f ? x : (__expf(x) - 1.f); }
__device__ __forceinline__ unsigned pk2(float a, float b) {
    __half2 h = __floats2half2_rn(a, b);
    return *(unsigned*)&h;
}

// ------------------------- weight folding ----------------------------------
__global__ void fold_w(const float* __restrict__ wg, const float* __restrict__ wv,
                       float* __restrict__ w2) {
    int o = blockIdx.x, j = threadIdx.x;
    float s = 0.f;
    for (int c = 0; c < CIN; c++) s += wg[o * CIN + c] * wv[c * CIN + j];
    w2[o * CIN + j] = s;
}
__global__ void fold_b(const float* __restrict__ wg, const float* __restrict__ bv,
                       float* __restrict__ b2) {
    int o = threadIdx.x;
    float s = 0.f;
    for (int c = 0; c < CIN; c++) s += wg[o * CIN + c] * bv[c];
    b2[o] = s;
}

// --------------- projections: SIMT fp32 GEMM, fp16 output ------------------
// transpose=1: out[b][n][o] (o contiguous, width CQK); else out[b][o][n]
__global__ __launch_bounds__(256) void proj_kernel(
    const float* __restrict__ W, const float* __restrict__ bias,
    const float* __restrict__ X, __half* __restrict__ out, int M, int transpose) {
    __shared__ float Ws[16][68];
    __shared__ float Xs[16][68];
    const int b = blockIdx.z, n0 = blockIdx.x * 64, o0 = blockIdx.y * 64;
    const float* Xb = X + (size_t)b * CIN * NPIX;
    const int t = threadIdx.x, tx = t % 16, ty = t / 16;
    float acc[4][4] = {};

    for (int c0 = 0; c0 < CIN; c0 += 16) {
        {
            int cc = t % 16, ob = t / 16;
#pragma unroll
            for (int r = 0; r < 4; r++) Ws[cc][ob + 16 * r] = W[(o0 + ob + 16 * r) * CIN + c0 + cc];
        }
        {
            int nn = t % 64, cb = t / 64;
#pragma unroll
            for (int r = 0; r < 4; r++)
                Xs[cb + 4 * r][nn] = Xb[(size_t)(c0 + cb + 4 * r) * NPIX + n0 + nn];
        }
        __syncthreads();
#pragma unroll
        for (int kk = 0; kk < 16; kk++) {
            float4 w4 = *(const float4*)&Ws[kk][ty * 4];
            float4 x4 = *(const float4*)&Xs[kk][tx * 4];
            float wa[4] = {w4.x, w4.y, w4.z, w4.w}, xa[4] = {x4.x, x4.y, x4.z, x4.w};
#pragma unroll
            for (int i = 0; i < 4; i++)
#pragma unroll
                for (int j = 0; j < 4; j++) acc[i][j] += wa[i] * xa[j];
        }
        __syncthreads();
    }
    float bo[4];
#pragma unroll
    for (int i = 0; i < 4; i++) bo[i] = bias[o0 + ty * 4 + i];

    if (transpose) {
#pragma unroll
        for (int j = 0; j < 4; j++) {
            int n = n0 + tx * 4 + j;
            uint2 u;
            u.x = pk2(acc[0][j] + bo[0], acc[1][j] + bo[1]);
            u.y = pk2(acc[2][j] + bo[2], acc[3][j] + bo[3]);
            *(uint2*)&out[((size_t)b * NPIX + n) * CQK + o0 + ty * 4] = u;
        }
    } else {
#pragma unroll
        for (int i = 0; i < 4; i++) {
            uint2 u;
            u.x = pk2(acc[i][0] + bo[i], acc[i][1] + bo[i]);
            u.y = pk2(acc[i][2] + bo[i], acc[i][3] + bo[i]);
            *(uint2*)&out[((size_t)b * M + o0 + ty * 4 + i) * NPIX + n0 + tx * 4] = u;
        }
    }
}

// --------- energy: Et[b][m][n] = elu(<k_m, q_n>)   (fp16, no /N) ----------
// CTA 256 thr, tile 128m x 128n, K=64. Warp grid 2(m) x 4(n), warp 64x32.
#define EST 72  // smem row stride in halves (144B, conflict-free)

__global__ __launch_bounds__(256) void energy_kernel(
    const __half* __restrict__ qg, const __half* __restrict__ kg,
    __half* __restrict__ eg) {
    __shared__ __half ks[128 * EST];
    __shared__ __half qs[128 * EST];
    const int tid = threadIdx.x, lane = tid & 31, w = tid >> 5;
    const int b = blockIdx.z, m0 = blockIdx.y * 128, n0 = blockIdx.x * 128;

    const uint4* kg4 = (const uint4*)(kg + ((size_t)b * NPIX + m0) * CQK);
    const uint4* qg4 = (const uint4*)(qg + ((size_t)b * NPIX + n0) * CQK);
#pragma unroll
    for (int it = 0; it < 4; it++) {
        int idx = tid + 256 * it;  // 1024 uint4 = 128 rows x 8
        int r = idx >> 3, s = idx & 7;
        *(uint4*)&ks[r * EST + s * 8] = kg4[idx];
        *(uint4*)&qs[r * EST + s * 8] = qg4[idx];
    }
    __syncthreads();

    const int wm = (w >> 2) * 64, wn = (w & 3) * 32;
    const uint32_t ksb = smem_u32(ks), qsb = smem_u32(qs);
    float d[4][4][4] = {};

#pragma unroll
    for (int kk = 0; kk < 4; kk++) {
        const int kofs = kk * 16;
        uint32_t a[4][4], bb[4][2];
#pragma unroll
        for (int i = 0; i < 4; i++) {
            int row = wm + i * 16 + (lane & 7) + ((lane >> 3) & 1) * 8;
            int col = kofs + (lane >> 4) * 8;
            ldsm_x4(a[i], ksb + (row * EST + col) * 2);
        }
#pragma unroll
        for (int j = 0; j < 4; j++) {
            int l = lane & 15;
            int row = wn + j * 8 + (l & 7);
            int col = kofs + (l >> 3) * 8;
            ldsm_x2(bb[j], qsb + (row * EST + col) * 2);
        }
#pragma unroll
        for (int i = 0; i < 4; i++)
#pragma unroll
            for (int j = 0; j < 4; j++) mma16816(d[i][j], a[i], bb[j]);
    }

    // epilogue: elu -> fp16 store
    const int mrow = m0 + wm + (lane >> 2);
    const int ncol = n0 + wn + (lane & 3) * 2;
#pragma unroll
    for (int i = 0; i < 4; i++) {
#pragma unroll
        for (int j = 0; j < 4; j++) {
            float* dd = d[i][j];
            unsigned u01 = pk2(eluf(dd[0]), eluf(dd[1]));
            unsigned u23 = pk2(eluf(dd[2]), eluf(dd[3]));
            size_t r0 = ((size_t)b * NPIX + mrow + i * 16) * NPIX + ncol + j * 8;
            size_t r1 = ((size_t)b * NPIX + mrow + i * 16 + 8) * NPIX + ncol + j * 8;
            *(unsigned*)&eg[r0] = u01;
            *(unsigned*)&eg[r1] = u23;
        }
    }
}

// ---- AV: out[b][c][m] = (sum_n v'[c][n] * Et[m][n]) / NPIX + bg[c] --------
// CTA 256 thr, tile 128c x 128m, K=4096 in 64-chunks, double-buffered smem.
#define AST 72
#define CHUNK 64
#define NCH (NPIX / CHUNK)
#define BUFH (256 * AST)  // halves per buffer: 128 A-rows + 128 B-rows

__global__ __launch_bounds__(256) void av_kernel(
    const __half* __restrict__ vg, const __half* __restrict__ eg,
    const float* __restrict__ bg, float* __restrict__ out) {
    extern __shared__ __half sm[];  // [2][BUFH]
    const int tid = threadIdx.x, lane = tid & 31, w = tid >> 5;
    const int c0 = blockIdx.x * 128, m0 = blockIdx.y * 128, b = blockIdx.z;

    const uint4* vg4 = (const uint4*)(vg + ((size_t)b * CIN + c0) * NPIX);   // row = 512 uint4
    const uint4* eg4 = (const uint4*)(eg + ((size_t)b * NPIX + m0) * NPIX);

    const int lr = tid >> 3, ls = tid & 7;  // 256 thr -> 32 rows x 8 cols per pass
    uint4 va[4], eb[4];

    auto load_regs = [&](int ch) {
#pragma unroll
        for (int tpass = 0; tpass < 4; tpass++) {
            int r = lr + 32 * tpass;
            va[tpass] = vg4[(size_t)r * 512 + ch * 8 + ls];
            eb[tpass] = eg4[(size_t)r * 512 + ch * 8 + ls];
        }
    };
    auto store_smem = [&](int p) {
        __half* A = sm + p * BUFH;
        __half* B = A + 128 * AST;
#pragma unroll
        for (int tpass = 0; tpass < 4; tpass++) {
            int r = lr + 32 * tpass;
            *(uint4*)&A[r * AST + ls * 8] = va[tpass];
            *(uint4*)&B[r * AST + ls * 8] = eb[tpass];
        }
    };

    load_regs(0);
    store_smem(0);
    load_regs(1);
    __syncthreads();

    const int wc = (w >> 2) * 64, wm = (w & 3) * 32;
    float d[4][4][4] = {};

    for (int ch = 0; ch < NCH; ch++) {
        const __half* A = sm + (ch & 1) * BUFH;
        const __half* B = A + 128 * AST;
        const uint32_t Ab = smem_u32(A), Bb = smem_u32(B);
#pragma unroll
        for (int kk = 0; kk < CHUNK / 16; kk++) {
            const int kofs = kk * 16;
            uint32_t a[4][4], bb[4][2];
#pragma unroll
            for (int i = 0; i < 4; i++) {
                int row = wc + i * 16 + (lane & 7) + ((lane >> 3) & 1) * 8;
                int col = kofs + (lane >> 4) * 8;
                ldsm_x4(a[i], Ab + (row * AST + col) * 2);
            }
#pragma unroll
            for (int j = 0; j < 4; j++) {
                int l = lane & 15;
                int row = wm + j * 8 + (l & 7);
                int col = kofs + (l >> 3) * 8;
                ldsm_x2(bb[j], Bb + (row * AST + col) * 2);
            }
#pragma unroll
            for (int i = 0; i < 4; i++)
#pragma unroll
                for (int j = 0; j < 4; j++) mma16816(d[i][j], a[i], bb[j]);
        }
        __syncthreads();
        if (ch + 1 < NCH) {
            store_smem((ch + 1) & 1);
            if (ch + 2 < NCH) load_regs(ch + 2);
            __syncthreads();
        }
    }

    // epilogue
    const float scale = 1.0f / (float)NPIX;
    const int crow = c0 + wc + (lane >> 2);
    const int mcol = m0 + wm + (lane & 3) * 2;
#pragma unroll
    for (int i = 0; i < 4; i++) {
        float bias0 = bg[crow + i * 16];
        float bias1 = bg[crow + i * 16 + 8];
#pragma unroll
        for (int j = 0; j < 4; j++) {
            float* dd = d[i][j];
            float2 r0 = make_float2(dd[0] * scale + bias0, dd[1] * scale + bias0);
            float2 r1 = make_float2(dd[2] * scale + bias1, dd[3] * scale + bias1);
            size_t o0 = ((size_t)b * CIN + crow + i * 16) * NPIX + mcol + j * 8;
            size_t o1 = ((size_t)b * CIN + crow + i * 16 + 8) * NPIX + mcol + j * 8;
            *(float2*)&out[o0] = r0;
            *(float2*)&out[o1] = r1;
        }
    }
}

// ------------------------------- launch -------------------------------------
extern "C" void kernel_launch(void* const* d_in, const int* in_sizes, int n_in,
                              void* d_out, int out_size) {
    const float* x  = (const float*)d_in[0];
    const float* wq = (const float*)d_in[1];
    const float* bq = (const float*)d_in[2];
    const float* wk = (const float*)d_in[3];
    const float* bk = (const float*)d_in[4];
    const float* wv = (const float*)d_in[5];
    const float* bv = (const float*)d_in[6];
    const float* wg = (const float*)d_in[7];
    const float* bg = (const float*)d_in[8];
    float* out = (float*)d_out;

    float *w2p, *b2p;
    __half *qp, *kp, *vp, *ep;
    cudaGetSymbolAddress((void**)&w2p, g_w2);
    cudaGetSymbolAddress((void**)&b2p, g_b2);
    cudaGetSymbolAddress((void**)&qp, g_q);
    cudaGetSymbolAddress((void**)&kp, g_k);
    cudaGetSymbolAddress((void**)&vp, g_v);
    cudaGetSymbolAddress((void**)&ep, g_e);

    const int AV_SMEM = 2 * BUFH * (int)sizeof(__half);  // 73728 B
    cudaFuncSetAttribute(av_kernel, cudaFuncAttributeMaxDynamicSharedMemorySize, AV_SMEM);

    fold_w<<<CIN, CIN>>>(wg, wv, w2p);
    fold_b<<<1, CIN>>>(wg, bv, b2p);

    proj_kernel<<<dim3(NPIX / 64, 1, BATCH), 256>>>(wq, bq, x, qp, CQK, 1);
    proj_kernel<<<dim3(NPIX / 64, 1, BATCH), 256>>>(wk, bk, x, kp, CQK, 1);
    proj_kernel<<<dim3(NPIX / 64, CIN / 64, BATCH), 256>>>(w2p, b2p, x, vp, CIN, 0);

    energy_kernel<<<dim3(NPIX / 128, NPIX / 128, BATCH), 256>>>(qp, kp, ep);
    av_kernel<<<dim3(CIN / 128, NPIX / 128, BATCH), 256, AV_SMEM>>>(vp, ep, bg, out);
}

// round 5
// speedup vs baseline: 6.2017x; 1.4503x over previous
#include <cuda_runtime.h>
#include <cuda_fp16.h>
#include <cstdint>

#define NPIX 4096
#define CIN  256
#define CQK  64
#define BATCH 4

// ------------------------- device scratch ----------------------------------
__device__ float  g_w2[CIN * CIN];
__device__ __half g_wc[384 * CIN];                   // [wq(64); wk(64); w2(256)] fp16
__device__ float  g_bc[384];                         // [bq; bk; b2]
__device__ __half g_q[(size_t)BATCH * NPIX * CQK];   // [b][n][o]
__device__ __half g_k[(size_t)BATCH * NPIX * CQK];   // [b][m][o]
__device__ __half g_v[(size_t)BATCH * CIN * NPIX];   // [b][c][n]
__device__ __half g_e[(size_t)BATCH * NPIX * NPIX];  // [b][m][n] = elu(energy), no /N

// ------------------------- helpers -----------------------------------------
__device__ __forceinline__ uint32_t smem_u32(const void* p) {
    uint32_t a;
    asm("{ .reg .u64 t; cvta.to.shared.u64 t, %1; cvt.u32.u64 %0, t; }" : "=r"(a) : "l"(p));
    return a;
}
__device__ __forceinline__ void ldsm_x4(uint32_t a[4], uint32_t addr) {
    asm volatile("ldmatrix.sync.aligned.m8n8.x4.shared.b16 {%0,%1,%2,%3}, [%4];"
                 : "=r"(a[0]), "=r"(a[1]), "=r"(a[2]), "=r"(a[3]) : "r"(addr));
}
__device__ __forceinline__ void ldsm_x2(uint32_t a[2], uint32_t addr) {
    asm volatile("ldmatrix.sync.aligned.m8n8.x2.shared.b16 {%0,%1}, [%2];"
                 : "=r"(a[0]), "=r"(a[1]) : "r"(addr));
}
__device__ __forceinline__ void ldsm_x4_t(uint32_t a[4], uint32_t addr) {
    asm volatile("ldmatrix.sync.aligned.m8n8.x4.trans.shared.b16 {%0,%1,%2,%3}, [%4];"
                 : "=r"(a[0]), "=r"(a[1]), "=r"(a[2]), "=r"(a[3]) : "r"(addr));
}
__device__ __forceinline__ void ldsm_x2_t(uint32_t a[2], uint32_t addr) {
    asm volatile("ldmatrix.sync.aligned.m8n8.x2.trans.shared.b16 {%0,%1}, [%2];"
                 : "=r"(a[0]), "=r"(a[1]) : "r"(addr));
}
__device__ __forceinline__ void mma16816(float d[4], const uint32_t a[4], const uint32_t b[2]) {
    asm volatile(
        "mma.sync.aligned.m16n8k16.row.col.f32.f16.f16.f32 "
        "{%0,%1,%2,%3}, {%4,%5,%6,%7}, {%8,%9}, {%0,%1,%2,%3};"
        : "+f"(d[0]), "+f"(d[1]), "+f"(d[2]), "+f"(d[3])
        : "r"(a[0]), "r"(a[1]), "r"(a[2]), "r"(a[3]), "r"(b[0]), "r"(b[1]));
}
__device__ __forceinline__ float eluf(float x) { return x > 0.f ? x : (__expf(x) - 1.f); }
__device__ __forceinline__ unsigned pk2(float a, float b) {
    __half2 h = __floats2half2_rn(a, b);
    return *(unsigned*)&h;
}

// ------------------------- weight folding / packing ------------------------
__global__ void fold_w(const float* __restrict__ wg, const float* __restrict__ wv,
                       float* __restrict__ w2) {
    int o = blockIdx.x, j = threadIdx.x;
    float s = 0.f;
    for (int c = 0; c < CIN; c++) s += wg[o * CIN + c] * wv[c * CIN + j];
    w2[o * CIN + j] = s;
}
__global__ void pack_weights(const float* __restrict__ wq, const float* __restrict__ wk,
                             const float* __restrict__ w2, const float* __restrict__ bq,
                             const float* __restrict__ bk, const float* __restrict__ wg,
                             const float* __restrict__ bv, __half* __restrict__ Wc,
                             float* __restrict__ bc) {
    int r = blockIdx.x, c = threadIdx.x;
    const float* src = r < 64 ? wq + r * CIN : (r < 128 ? wk + (r - 64) * CIN : w2 + (r - 128) * CIN);
    Wc[r * CIN + c] = __float2half(src[c]);
    if (c == 0) {
        if (r < 64) bc[r] = bq[r];
        else if (r < 128) bc[r] = bk[r - 64];
        else {  // b2[o] = sum_c wg[o][c] * bv[c]
            float s = 0.f;
            int o = r - 128;
            for (int cc = 0; cc < CIN; cc++) s += wg[o * CIN + cc] * bv[cc];
            bc[r] = s;
        }
    }
}

// ----------------- fused QKV projection (HMMA, fp16) -----------------------
// wtile0: qt/kt[n][o] = x^T W^T (A = x^T via ldmatrix.trans). wtile1,2: v[c][n].
#define XST 136  // [64 c][128 n] stride (halves)
#define WST 72   // [128 row][64 c] stride

__global__ __launch_bounds__(256) void proj_qkv(
    const float* __restrict__ X, const __half* __restrict__ Wc,
    const float* __restrict__ bc, __half* __restrict__ qout,
    __half* __restrict__ kout, __half* __restrict__ vout) {
    __shared__ __align__(16) __half XT[64 * XST];   // [c][n]
    __shared__ __align__(16) __half WT[128 * WST];  // [row][c]
    const int tid = threadIdx.x, lane = tid & 31, w = tid >> 5;
    const int wtile = blockIdx.x, n0 = blockIdx.y * 128, b = blockIdx.z;
    const float* Xb = X + (size_t)b * CIN * NPIX;
    const __half* Wrow = Wc + (size_t)wtile * 128 * CIN;

    const int wa = (w >> 2) * 64, wb = (w & 3) * 32;
    const uint32_t XTb = smem_u32(XT), WTb = smem_u32(WT);
    float d[4][4][4] = {};

    for (int ck = 0; ck < 4; ck++) {
        const int c0 = ck * 64;
        // XT [c][n]: natural layout, fp32->fp16 in flight, 8B stores
#pragma unroll
        for (int it = 0; it < 8; it++) {
            int idx = it * 256 + tid;
            int cc = idx >> 5, ng = idx & 31;
            float4 x4 = *(const float4*)&Xb[(size_t)(c0 + cc) * NPIX + n0 + ng * 4];
            uint2 u;
            u.x = pk2(x4.x, x4.y);
            u.y = pk2(x4.z, x4.w);
            *(uint2*)&XT[cc * XST + ng * 4] = u;
        }
        // WT [row][c]: direct uint4 copy
#pragma unroll
        for (int it = 0; it < 4; it++) {
            int idx = it * 256 + tid;
            int r = idx >> 3, g = idx & 7;
            *(uint4*)&WT[r * WST + g * 8] = *(const uint4*)&Wrow[(size_t)r * CIN + c0 + g * 8];
        }
        __syncthreads();

        if (wtile == 0) {
            // A = x^T (rows n) via trans-ldsm on XT[c][n]; B = W (rows o) natural
#pragma unroll
            for (int kk = 0; kk < 4; kk++) {
                const int kofs = kk * 16;
                uint32_t a[4][4], bb[4][2];
#pragma unroll
                for (int i = 0; i < 4; i++) {
                    int rc = kofs + (lane & 7) + (lane >> 4) * 8;
                    int cn = wa + i * 16 + ((lane >> 3) & 1) * 8;
                    ldsm_x4_t(a[i], XTb + (rc * XST + cn) * 2);
                }
#pragma unroll
                for (int j = 0; j < 4; j++) {
                    int l = lane & 15;
                    int row = wb + j * 8 + (l & 7);
                    int col = kofs + (l >> 3) * 8;
                    ldsm_x2(bb[j], WTb + (row * WST + col) * 2);
                }
#pragma unroll
                for (int i = 0; i < 4; i++)
#pragma unroll
                    for (int j = 0; j < 4; j++) mma16816(d[i][j], a[i], bb[j]);
            }
        } else {
            // A = W (rows c) natural; B = x^T (cols n) via trans-ldsm on XT
#pragma unroll
            for (int kk = 0; kk < 4; kk++) {
                const int kofs = kk * 16;
                uint32_t a[4][4], bb[4][2];
#pragma unroll
                for (int i = 0; i < 4; i++) {
                    int row = wa + i * 16 + (lane & 7) + ((lane >> 3) & 1) * 8;
                    int col = kofs + (lane >> 4) * 8;
                    ldsm_x4(a[i], WTb + (row * WST + col) * 2);
                }
#pragma unroll
                for (int j = 0; j < 4; j++) {
                    int l = lane & 15;
                    int rc = kofs + l;
                    int cn = wb + j * 8;
                    ldsm_x2_t(bb[j], XTb + (rc * XST + cn) * 2);
                }
#pragma unroll
                for (int i = 0; i < 4; i++)
#pragma unroll
                    for (int j = 0; j < 4; j++) mma16816(d[i][j], a[i], bb[j]);
            }
        }
        __syncthreads();
    }

    if (wtile == 0) {  // rows = n, cols = o (q: o<64, k: o>=64)
#pragma unroll
        for (int j = 0; j < 4; j++) {
            int o = wb + j * 8 + (lane & 3) * 2;
            float b0 = bc[o], b1 = bc[o + 1];
            __half* dst = o < 64 ? qout : kout;
            int oo = o < 64 ? o : o - 64;
#pragma unroll
            for (int i = 0; i < 4; i++) {
                int n = n0 + wa + i * 16 + (lane >> 2);
                float* dd = d[i][j];
                *(unsigned*)&dst[((size_t)b * NPIX + n) * CQK + oo] = pk2(dd[0] + b0, dd[1] + b1);
                *(unsigned*)&dst[((size_t)b * NPIX + n + 8) * CQK + oo] = pk2(dd[2] + b0, dd[3] + b1);
            }
        }
    } else {  // rows = c, cols = n
#pragma unroll
        for (int i = 0; i < 4; i++) {
            int c = (wtile - 1) * 128 + wa + i * 16 + (lane >> 2);
            float b0 = bc[128 + c], b1 = bc[128 + c + 8];
#pragma unroll
            for (int j = 0; j < 4; j++) {
                int n = n0 + wb + j * 8 + (lane & 3) * 2;
                float* dd = d[i][j];
                *(unsigned*)&vout[((size_t)b * CIN + c) * NPIX + n] = pk2(dd[0] + b0, dd[1] + b0);
                *(unsigned*)&vout[((size_t)b * CIN + c + 8) * NPIX + n] = pk2(dd[2] + b1, dd[3] + b1);
            }
        }
    }
}

// --------- energy: Et[b][m][n] = elu(<k_m, q_n>)   (fp16, no /N) ----------
#define EST 72

__global__ __launch_bounds__(256) void energy_kernel(
    const __half* __restrict__ qg, const __half* __restrict__ kg,
    __half* __restrict__ eg) {
    __shared__ __half ks[128 * EST];
    __shared__ __half qs[128 * EST];
    const int tid = threadIdx.x, lane = tid & 31, w = tid >> 5;
    const int b = blockIdx.z, m0 = blockIdx.y * 128, n0 = blockIdx.x * 128;

    const uint4* kg4 = (const uint4*)(kg + ((size_t)b * NPIX + m0) * CQK);
    const uint4* qg4 = (const uint4*)(qg + ((size_t)b * NPIX + n0) * CQK);
#pragma unroll
    for (int it = 0; it < 4; it++) {
        int idx = tid + 256 * it;
        int r = idx >> 3, s = idx & 7;
        *(uint4*)&ks[r * EST + s * 8] = kg4[idx];
        *(uint4*)&qs[r * EST + s * 8] = qg4[idx];
    }
    __syncthreads();

    const int wm = (w >> 2) * 64, wn = (w & 3) * 32;
    const uint32_t ksb = smem_u32(ks), qsb = smem_u32(qs);
    float d[4][4][4] = {};

#pragma unroll
    for (int kk = 0; kk < 4; kk++) {
        const int kofs = kk * 16;
        uint32_t a[4][4], bb[4][2];
#pragma unroll
        for (int i = 0; i < 4; i++) {
            int row = wm + i * 16 + (lane & 7) + ((lane >> 3) & 1) * 8;
            int col = kofs + (lane >> 4) * 8;
            ldsm_x4(a[i], ksb + (row * EST + col) * 2);
        }
#pragma unroll
        for (int j = 0; j < 4; j++) {
            int l = lane & 15;
            int row = wn + j * 8 + (l & 7);
            int col = kofs + (l >> 3) * 8;
            ldsm_x2(bb[j], qsb + (row * EST + col) * 2);
        }
#pragma unroll
        for (int i = 0; i < 4; i++)
#pragma unroll
            for (int j = 0; j < 4; j++) mma16816(d[i][j], a[i], bb[j]);
    }

    const int mrow = m0 + wm + (lane >> 2);
    const int ncol = n0 + wn + (lane & 3) * 2;
#pragma unroll
    for (int i = 0; i < 4; i++) {
#pragma unroll
        for (int j = 0; j < 4; j++) {
            float* dd = d[i][j];
            unsigned u01 = pk2(eluf(dd[0]), eluf(dd[1]));
            unsigned u23 = pk2(eluf(dd[2]), eluf(dd[3]));
            size_t r0 = ((size_t)b * NPIX + mrow + i * 16) * NPIX + ncol + j * 8;
            size_t r1 = ((size_t)b * NPIX + mrow + i * 16 + 8) * NPIX + ncol + j * 8;
            *(unsigned*)&eg[r0] = u01;
            *(unsigned*)&eg[r1] = u23;
        }
    }
}

// ---- AV: out[b][c][m] = (sum_n v'[c][n] * Et[m][n]) / NPIX + bg[c] --------
#define AST 72
#define CHUNK 64
#define NCH (NPIX / CHUNK)
#define BUFH (256 * AST)

__global__ __launch_bounds__(256) void av_kernel(
    const __half* __restrict__ vg, const __half* __restrict__ eg,
    const float* __restrict__ bg, float* __restrict__ out) {
    extern __shared__ __half sm[];
    const int tid = threadIdx.x, lane = tid & 31, w = tid >> 5;
    const int c0 = blockIdx.x * 128, m0 = blockIdx.y * 128, b = blockIdx.z;

    const uint4* vg4 = (const uint4*)(vg + ((size_t)b * CIN + c0) * NPIX);
    const uint4* eg4 = (const uint4*)(eg + ((size_t)b * NPIX + m0) * NPIX);

    const int lr = tid >> 3, ls = tid & 7;
    uint4 va[4], eb[4];

    auto load_regs = [&](int ch) {
#pragma unroll
        for (int tp = 0; tp < 4; tp++) {
            int r = lr + 32 * tp;
            va[tp] = vg4[(size_t)r * 512 + ch * 8 + ls];
            eb[tp] = eg4[(size_t)r * 512 + ch * 8 + ls];
        }
    };
    auto store_smem = [&](int p) {
        __half* A = sm + p * BUFH;
        __half* B = A + 128 * AST;
#pragma unroll
        for (int tp = 0; tp < 4; tp++) {
            int r = lr + 32 * tp;
            *(uint4*)&A[r * AST + ls * 8] = va[tp];
            *(uint4*)&B[r * AST + ls * 8] = eb[tp];
        }
    };

    load_regs(0);
    store_smem(0);
    load_regs(1);
    __syncthreads();

    const int wc = (w >> 2) * 64, wm = (w & 3) * 32;
    float d[4][4][4] = {};

    for (int ch = 0; ch < NCH; ch++) {
        const __half* A = sm + (ch & 1) * BUFH;
        const __half* B = A + 128 * AST;
        const uint32_t Ab = smem_u32(A), Bb = smem_u32(B);
#pragma unroll
        for (int kk = 0; kk < CHUNK / 16; kk++) {
            const int kofs = kk * 16;
            uint32_t a[4][4], bb[4][2];
#pragma unroll
            for (int i = 0; i < 4; i++) {
                int row = wc + i * 16 + (lane & 7) + ((lane >> 3) & 1) * 8;
                int col = kofs + (lane >> 4) * 8;
                ldsm_x4(a[i], Ab + (row * AST + col) * 2);
            }
#pragma unroll
            for (int j = 0; j < 4; j++) {
                int l = lane & 15;
                int row = wm + j * 8 + (l & 7);
                int col = kofs + (l >> 3) * 8;
                ldsm_x2(bb[j], Bb + (row * AST + col) * 2);
            }
#pragma unroll
            for (int i = 0; i < 4; i++)
#pragma unroll
                for (int j = 0; j < 4; j++) mma16816(d[i][j], a[i], bb[j]);
        }
        __syncthreads();
        if (ch + 1 < NCH) {
            store_smem((ch + 1) & 1);
            if (ch + 2 < NCH) load_regs(ch + 2);
            __syncthreads();
        }
    }

    const float scale = 1.0f / (float)NPIX;
    const int crow = c0 + wc + (lane >> 2);
    const int mcol = m0 + wm + (lane & 3) * 2;
#pragma unroll
    for (int i = 0; i < 4; i++) {
        float bias0 = bg[crow + i * 16];
        float bias1 = bg[crow + i * 16 + 8];
#pragma unroll
        for (int j = 0; j < 4; j++) {
            float* dd = d[i][j];
            float2 r0 = make_float2(dd[0] * scale + bias0, dd[1] * scale + bias0);
            float2 r1 = make_float2(dd[2] * scale + bias1, dd[3] * scale + bias1);
            size_t o0 = ((size_t)b * CIN + crow + i * 16) * NPIX + mcol + j * 8;
            size_t o1 = ((size_t)b * CIN + crow + i * 16 + 8) * NPIX + mcol + j * 8;
            *(float2*)&out[o0] = r0;
            *(float2*)&out[o1] = r1;
        }
    }
}

// ------------------------------- launch -------------------------------------
extern "C" void kernel_launch(void* const* d_in, const int* in_sizes, int n_in,
                              void* d_out, int out_size) {
    const float* x  = (const float*)d_in[0];
    const float* wq = (const float*)d_in[1];
    const float* bq = (const float*)d_in[2];
    const float* wk = (const float*)d_in[3];
    const float* bk = (const float*)d_in[4];
    const float* wv = (const float*)d_in[5];
    const float* bv = (const float*)d_in[6];
    const float* wg = (const float*)d_in[7];
    const float* bg = (const float*)d_in[8];
    float* out = (float*)d_out;

    float *w2p, *bcp;
    __half *wcp, *qp, *kp, *vp, *ep;
    cudaGetSymbolAddress((void**)&w2p, g_w2);
    cudaGetSymbolAddress((void**)&wcp, g_wc);
    cudaGetSymbolAddress((void**)&bcp, g_bc);
    cudaGetSymbolAddress((void**)&qp, g_q);
    cudaGetSymbolAddress((void**)&kp, g_k);
    cudaGetSymbolAddress((void**)&vp, g_v);
    cudaGetSymbolAddress((void**)&ep, g_e);

    const int AV_SMEM = 2 * BUFH * (int)sizeof(__half);
    cudaFuncSetAttribute(av_kernel, cudaFuncAttributeMaxDynamicSharedMemorySize, AV_SMEM);

    fold_w<<<CIN, CIN>>>(wg, wv, w2p);
    pack_weights<<<384, CIN>>>(wq, wk, w2p, bq, bk, wg, bv, wcp, bcp);

    proj_qkv<<<dim3(3, NPIX / 128, BATCH), 256>>>(x, wcp, bcp, qp, kp, vp);

    energy_kernel<<<dim3(NPIX / 128, NPIX / 128, BATCH), 256>>>(qp, kp, ep);
    av_kernel<<<dim3(CIN / 128, NPIX / 128, BATCH), 256, AV_SMEM>>>(vp, ep, bg, out);
}

// round 6
// speedup vs baseline: 7.6370x; 1.2314x over previous
#include <cuda_runtime.h>
#include <cuda_fp16.h>
#include <cstdint>

#define NPIX 4096
#define CIN  256
#define CQK  64
#define BATCH 4
#define NCH  (NPIX / 64)

// ------------------------- device scratch ----------------------------------
__device__ float  g_w2[CIN * CIN];
__device__ __half g_wc[384 * CIN];                   // [wq(64); wk(64); w2(256)] fp16
__device__ float  g_bc[384];                         // [bq; bk; b2]
__device__ __half g_q[(size_t)BATCH * NPIX * CQK];   // [b][n][o]
__device__ __half g_k[(size_t)BATCH * NPIX * CQK];   // [b][m][o]
__device__ __half g_v[(size_t)BATCH * CIN * NPIX];   // [b][c][n]

// ------------------------- helpers -----------------------------------------
__device__ __forceinline__ uint32_t smem_u32(const void* p) {
    uint32_t a;
    asm("{ .reg .u64 t; cvta.to.shared.u64 t, %1; cvt.u32.u64 %0, t; }" : "=r"(a) : "l"(p));
    return a;
}
__device__ __forceinline__ void ldsm_x4(uint32_t a[4], uint32_t addr) {
    asm volatile("ldmatrix.sync.aligned.m8n8.x4.shared.b16 {%0,%1,%2,%3}, [%4];"
                 : "=r"(a[0]), "=r"(a[1]), "=r"(a[2]), "=r"(a[3]) : "r"(addr));
}
__device__ __forceinline__ void ldsm_x2(uint32_t a[2], uint32_t addr) {
    asm volatile("ldmatrix.sync.aligned.m8n8.x2.shared.b16 {%0,%1}, [%2];"
                 : "=r"(a[0]), "=r"(a[1]) : "r"(addr));
}
__device__ __forceinline__ void ldsm_x4_t(uint32_t a[4], uint32_t addr) {
    asm volatile("ldmatrix.sync.aligned.m8n8.x4.trans.shared.b16 {%0,%1,%2,%3}, [%4];"
                 : "=r"(a[0]), "=r"(a[1]), "=r"(a[2]), "=r"(a[3]) : "r"(addr));
}
__device__ __forceinline__ void ldsm_x2_t(uint32_t a[2], uint32_t addr) {
    asm volatile("ldmatrix.sync.aligned.m8n8.x2.trans.shared.b16 {%0,%1}, [%2];"
                 : "=r"(a[0]), "=r"(a[1]) : "r"(addr));
}
__device__ __forceinline__ void mma16816(float d[4], const uint32_t a[4], const uint32_t b[2]) {
    asm volatile(
        "mma.sync.aligned.m16n8k16.row.col.f32.f16.f16.f32 "
        "{%0,%1,%2,%3}, {%4,%5,%6,%7}, {%8,%9}, {%0,%1,%2,%3};"
        : "+f"(d[0]), "+f"(d[1]), "+f"(d[2]), "+f"(d[3])
        : "r"(a[0]), "r"(a[1]), "r"(a[2]), "r"(a[3]), "r"(b[0]), "r"(b[1]));
}
#define CP_ASYNC16(dst, src) \
    asm volatile("cp.async.cg.shared.global [%0], [%1], 16;" :: "r"(dst), "l"(src))
#define CP_COMMIT() asm volatile("cp.async.commit_group;" ::: "memory")
#define CP_WAIT(n)  asm volatile("cp.async.wait_group %0;" :: "n"(n) : "memory")

__device__ __forceinline__ float eluf(float x) { return x > 0.f ? x : (__expf(x) - 1.f); }
__device__ __forceinline__ unsigned pk2(float a, float b) {
    __half2 h = __floats2half2_rn(a, b);
    return *(unsigned*)&h;
}

// ------------------------- weight folding / packing ------------------------
__global__ void fold_w(const float* __restrict__ wg, const float* __restrict__ wv,
                       float* __restrict__ w2) {
    int o = blockIdx.x, j = threadIdx.x;
    float s = 0.f;
    for (int c = 0; c < CIN; c++) s += wg[o * CIN + c] * wv[c * CIN + j];
    w2[o * CIN + j] = s;
}
__global__ void pack_weights(const float* __restrict__ wq, const float* __restrict__ wk,
                             const float* __restrict__ w2, const float* __restrict__ bq,
                             const float* __restrict__ bk, const float* __restrict__ wg,
                             const float* __restrict__ bv, __half* __restrict__ Wc,
                             float* __restrict__ bc) {
    int r = blockIdx.x, c = threadIdx.x;
    const float* src = r < 64 ? wq + r * CIN : (r < 128 ? wk + (r - 64) * CIN : w2 + (r - 128) * CIN);
    Wc[r * CIN + c] = __float2half(src[c]);
    if (c == 0) {
        if (r < 64) bc[r] = bq[r];
        else if (r < 128) bc[r] = bk[r - 64];
        else {
            float s = 0.f;
            int o = r - 128;
            for (int cc = 0; cc < CIN; cc++) s += wg[o * CIN + cc] * bv[cc];
            bc[r] = s;
        }
    }
}

// ----------------- fused QKV projection (HMMA, fp16) -----------------------
#define XST 136
#define WST 72

__global__ __launch_bounds__(256) void proj_qkv(
    const float* __restrict__ X, const __half* __restrict__ Wc,
    const float* __restrict__ bc, __half* __restrict__ qout,
    __half* __restrict__ kout, __half* __restrict__ vout) {
    __shared__ __align__(16) __half XT[64 * XST];
    __shared__ __align__(16) __half WT[128 * WST];
    const int tid = threadIdx.x, lane = tid & 31, w = tid >> 5;
    const int wtile = blockIdx.x, n0 = blockIdx.y * 128, b = blockIdx.z;
    const float* Xb = X + (size_t)b * CIN * NPIX;
    const __half* Wrow = Wc + (size_t)wtile * 128 * CIN;

    const int wa = (w >> 2) * 64, wb = (w & 3) * 32;
    const uint32_t XTb = smem_u32(XT), WTb = smem_u32(WT);
    float d[4][4][4] = {};

    for (int ck = 0; ck < 4; ck++) {
        const int c0 = ck * 64;
#pragma unroll
        for (int it = 0; it < 8; it++) {
            int idx = it * 256 + tid;
            int cc = idx >> 5, ng = idx & 31;
            float4 x4 = *(const float4*)&Xb[(size_t)(c0 + cc) * NPIX + n0 + ng * 4];
            uint2 u;
            u.x = pk2(x4.x, x4.y);
            u.y = pk2(x4.z, x4.w);
            *(uint2*)&XT[cc * XST + ng * 4] = u;
        }
#pragma unroll
        for (int it = 0; it < 4; it++) {
            int idx = it * 256 + tid;
            int r = idx >> 3, g = idx & 7;
            *(uint4*)&WT[r * WST + g * 8] = *(const uint4*)&Wrow[(size_t)r * CIN + c0 + g * 8];
        }
        __syncthreads();

        if (wtile == 0) {
#pragma unroll
            for (int kk = 0; kk < 4; kk++) {
                const int kofs = kk * 16;
                uint32_t a[4][4], bb[4][2];
#pragma unroll
                for (int i = 0; i < 4; i++) {
                    int rc = kofs + (lane & 7) + (lane >> 4) * 8;
                    int cn = wa + i * 16 + ((lane >> 3) & 1) * 8;
                    ldsm_x4_t(a[i], XTb + (rc * XST + cn) * 2);
                }
#pragma unroll
                for (int j = 0; j < 4; j++) {
                    int l = lane & 15;
                    int row = wb + j * 8 + (l & 7);
                    int col = kofs + (l >> 3) * 8;
                    ldsm_x2(bb[j], WTb + (row * WST + col) * 2);
                }
#pragma unroll
                for (int i = 0; i < 4; i++)
#pragma unroll
                    for (int j = 0; j < 4; j++) mma16816(d[i][j], a[i], bb[j]);
            }
        } else {
#pragma unroll
            for (int kk = 0; kk < 4; kk++) {
                const int kofs = kk * 16;
                uint32_t a[4][4], bb[4][2];
#pragma unroll
                for (int i = 0; i < 4; i++) {
                    int row = wa + i * 16 + (lane & 7) + ((lane >> 3) & 1) * 8;
                    int col = kofs + (lane >> 4) * 8;
                    ldsm_x4(a[i], WTb + (row * WST + col) * 2);
                }
#pragma unroll
                for (int j = 0; j < 4; j++) {
                    int l = lane & 15;
                    int rc = kofs + l;
                    int cn = wb + j * 8;
                    ldsm_x2_t(bb[j], XTb + (rc * XST + cn) * 2);
                }
#pragma unroll
                for (int i = 0; i < 4; i++)
#pragma unroll
                    for (int j = 0; j < 4; j++) mma16816(d[i][j], a[i], bb[j]);
            }
        }
        __syncthreads();
    }

    if (wtile == 0) {
#pragma unroll
        for (int j = 0; j < 4; j++) {
            int o = wb + j * 8 + (lane & 3) * 2;
            float b0 = bc[o], b1 = bc[o + 1];
            __half* dst = o < 64 ? qout : kout;
            int oo = o < 64 ? o : o - 64;
#pragma unroll
            for (int i = 0; i < 4; i++) {
                int n = n0 + wa + i * 16 + (lane >> 2);
                float* dd = d[i][j];
                *(unsigned*)&dst[((size_t)b * NPIX + n) * CQK + oo] = pk2(dd[0] + b0, dd[1] + b1);
                *(unsigned*)&dst[((size_t)b * NPIX + n + 8) * CQK + oo] = pk2(dd[2] + b0, dd[3] + b1);
            }
        }
    } else {
#pragma unroll
        for (int i = 0; i < 4; i++) {
            int c = (wtile - 1) * 128 + wa + i * 16 + (lane >> 2);
            float b0 = bc[128 + c], b1 = bc[128 + c + 8];
#pragma unroll
            for (int j = 0; j < 4; j++) {
                int n = n0 + wb + j * 8 + (lane & 3) * 2;
                float* dd = d[i][j];
                *(unsigned*)&vout[((size_t)b * CIN + c) * NPIX + n] = pk2(dd[0] + b0, dd[1] + b0);
                *(unsigned*)&vout[((size_t)b * CIN + c + 8) * NPIX + n] = pk2(dd[2] + b1, dd[3] + b1);
            }
        }
    }
}

// ------------- fused attention: energy + AV, E never hits DRAM -------------
// CTA = (m-tile 128, batch). Output tile 256c x 128m fp32.
// Loop n in 64-chunks: cp.async q[64n][64o], v[256c][64n] (double buffered);
// E[128m][64n] = elu(k.q^T) via HMMA -> fp16 smem; acc += v.E^T via HMMA.
#define FST 72
#define K_OFF 0
#define E_OFF (128 * FST)
#define Q_OFF (2 * 128 * FST)
#define QBUF  (64 * FST)
#define V_OFF (Q_OFF + 2 * QBUF)
#define VBUF  (256 * FST)
#define TOT_H (V_OFF + 2 * VBUF)  // 64512 halves = 129024 B

__global__ __launch_bounds__(256, 1) void fused_attn(
    const __half* __restrict__ qg, const __half* __restrict__ kg,
    const __half* __restrict__ vg, const float* __restrict__ bgb,
    float* __restrict__ out) {
    extern __shared__ __half sm[];
    const int tid = threadIdx.x, lane = tid & 31, w = tid >> 5;
    const int m0 = blockIdx.x * 128, b = blockIdx.y;
    const uint32_t smb = smem_u32(sm);

    // k tile [128 m][64 o], resident for the whole CTA
    const uint4* kg4 = (const uint4*)(kg + ((size_t)b * NPIX + m0) * CQK);
#pragma unroll
    for (int it = 0; it < 4; it++) {
        int idx = tid + 256 * it;
        int r = idx >> 3, s = idx & 7;
        *(uint4*)&sm[K_OFF + r * FST + s * 8] = kg4[idx];
    }

    const __half* qgb = qg + (size_t)b * NPIX * CQK;
    const __half* vgb = vg + (size_t)b * CIN * NPIX;

    auto prefetch = [&](int ch) {
        const int p = ch & 1;
        const int n0 = ch * 64;
        const uint32_t qdst = smb + (Q_OFF + p * QBUF) * 2;
#pragma unroll
        for (int it = 0; it < 2; it++) {
            int idx = tid + 256 * it;
            int r = idx >> 3, s = idx & 7;
            CP_ASYNC16(qdst + (r * FST + s * 8) * 2, qgb + (size_t)(n0 + r) * CQK + s * 8);
        }
        const uint32_t vdst = smb + (V_OFF + p * VBUF) * 2;
#pragma unroll
        for (int it = 0; it < 8; it++) {
            int idx = tid + 256 * it;
            int r = idx >> 3, s = idx & 7;
            CP_ASYNC16(vdst + (r * FST + s * 8) * 2, vgb + (size_t)r * NPIX + n0 + s * 8);
        }
        CP_COMMIT();
    };

    prefetch(0);
    prefetch(1);

    const int wme = (w >> 2) * 64, wne = (w & 3) * 16;  // energy warp tile 64m x 16n
    const int wc  = (w >> 1) * 64, wmm = (w & 1) * 64;  // AV warp tile 64c x 64m
    const uint32_t ksb = smb + K_OFF * 2;
    const uint32_t esb = smb + E_OFF * 2;

    float acc[4][8][4] = {};

    for (int ch = 0; ch < NCH; ch++) {
        const int p = ch & 1;
        const uint32_t qsb = smb + (Q_OFF + p * QBUF) * 2;
        const uint32_t vsb = smb + (V_OFF + p * VBUF) * 2;

        if (ch == NCH - 1) CP_WAIT(0); else CP_WAIT(1);
        __syncthreads();

        // ---- energy stage: E[128m][64n] = elu(k . q^T)
        float de[4][2][4] = {};
#pragma unroll
        for (int kk = 0; kk < 4; kk++) {
            const int ko = kk * 16;
            uint32_t a[4][4], bb[2][2];
#pragma unroll
            for (int i = 0; i < 4; i++) {
                int row = wme + i * 16 + (lane & 7) + ((lane >> 3) & 1) * 8;
                int col = ko + (lane >> 4) * 8;
                ldsm_x4(a[i], ksb + (row * FST + col) * 2);
            }
#pragma unroll
            for (int j = 0; j < 2; j++) {
                int l = lane & 15;
                int row = wne + j * 8 + (l & 7);
                int col = ko + (l >> 3) * 8;
                ldsm_x2(bb[j], qsb + (row * FST + col) * 2);
            }
#pragma unroll
            for (int i = 0; i < 4; i++)
#pragma unroll
                for (int j = 0; j < 2; j++) mma16816(de[i][j], a[i], bb[j]);
        }
#pragma unroll
        for (int i = 0; i < 4; i++) {
            int m = wme + i * 16 + (lane >> 2);
#pragma unroll
            for (int j = 0; j < 2; j++) {
                int n = wne + j * 8 + (lane & 3) * 2;
                float* dd = de[i][j];
                *(unsigned*)&sm[E_OFF + m * FST + n]       = pk2(eluf(dd[0]), eluf(dd[1]));
                *(unsigned*)&sm[E_OFF + (m + 8) * FST + n] = pk2(eluf(dd[2]), eluf(dd[3]));
            }
        }
        __syncthreads();

        // ---- AV stage: acc[c][m] += v . E^T
#pragma unroll
        for (int kk = 0; kk < 4; kk++) {
            const int ko = kk * 16;
            uint32_t a[4][4], bb[8][2];
#pragma unroll
            for (int i = 0; i < 4; i++) {
                int row = wc + i * 16 + (lane & 7) + ((lane >> 3) & 1) * 8;
                int col = ko + (lane >> 4) * 8;
                ldsm_x4(a[i], vsb + (row * FST + col) * 2);
            }
#pragma unroll
            for (int j = 0; j < 8; j++) {
                int l = lane & 15;
                int row = wmm + j * 8 + (l & 7);
                int col = ko + (l >> 3) * 8;
                ldsm_x2(bb[j], esb + (row * FST + col) * 2);
            }
#pragma unroll
            for (int i = 0; i < 4; i++)
#pragma unroll
                for (int j = 0; j < 8; j++) mma16816(acc[i][j], a[i], bb[j]);
        }
        __syncthreads();

        if (ch + 2 < NCH) prefetch(ch + 2);
    }

    // ---- epilogue: /N + bias
    const float scale = 1.0f / (float)NPIX;
#pragma unroll
    for (int i = 0; i < 4; i++) {
        int c = wc + i * 16 + (lane >> 2);
        float b0 = bgb[c], b1 = bgb[c + 8];
#pragma unroll
        for (int j = 0; j < 8; j++) {
            int m = m0 + wmm + j * 8 + (lane & 3) * 2;
            float* dd = acc[i][j];
            *(float2*)&out[((size_t)b * CIN + c) * NPIX + m] =
                make_float2(dd[0] * scale + b0, dd[1] * scale + b0);
            *(float2*)&out[((size_t)b * CIN + c + 8) * NPIX + m] =
                make_float2(dd[2] * scale + b1, dd[3] * scale + b1);
        }
    }
}

// ------------------------------- launch -------------------------------------
extern "C" void kernel_launch(void* const* d_in, const int* in_sizes, int n_in,
                              void* d_out, int out_size) {
    const float* x  = (const float*)d_in[0];
    const float* wq = (const float*)d_in[1];
    const float* bq = (const float*)d_in[2];
    const float* wk = (const float*)d_in[3];
    const float* bk = (const float*)d_in[4];
    const float* wv = (const float*)d_in[5];
    const float* bv = (const float*)d_in[6];
    const float* wg = (const float*)d_in[7];
    const float* bg = (const float*)d_in[8];
    float* out = (float*)d_out;

    float *w2p, *bcp;
    __half *wcp, *qp, *kp, *vp;
    cudaGetSymbolAddress((void**)&w2p, g_w2);
    cudaGetSymbolAddress((void**)&wcp, g_wc);
    cudaGetSymbolAddress((void**)&bcp, g_bc);
    cudaGetSymbolAddress((void**)&qp, g_q);
    cudaGetSymbolAddress((void**)&kp, g_k);
    cudaGetSymbolAddress((void**)&vp, g_v);

    const int F_SMEM = TOT_H * (int)sizeof(__half);  // 129024
    cudaFuncSetAttribute(fused_attn, cudaFuncAttributeMaxDynamicSharedMemorySize, F_SMEM);

    fold_w<<<CIN, CIN>>>(wg, wv, w2p);
    pack_weights<<<384, CIN>>>(wq, wk, w2p, bq, bk, wg, bv, wcp, bcp);

    proj_qkv<<<dim3(3, NPIX / 128, BATCH), 256>>>(x, wcp, bcp, qp, kp, vp);

    fused_attn<<<dim3(NPIX / 128, BATCH), 256, F_SMEM>>>(qp, kp, vp, bg, out);
}